// round 9
// baseline (speedup 1.0000x reference)
#include <cuda_runtime.h>

#define LRELU(v) ((v) >= 0.f ? (v) : 0.01f*(v))

constexpr int B_=8, T_=60, S_=36, H_=4, E_=16, PE_=16, AD_=12, D_=28, TA_=10, C_=32, OH_=16;
constexpr int BH = B_*H_;         // 32
constexpr int SS = S_*S_;         // 1296
constexpr int KEEP = 648;         // floor(S*S*0.5)
constexpr float EPSf = 1e-5f;

// ---------------- device scratch ----------------
__device__ float g_pe[B_*T_*PE_];
__device__ float g_cnt[B_*S_];
__device__ float g_h[BH*T_*S_*E_];       // (b,h,t,s,e)
__device__ float g_alpha[BH*T_*SS];      // (b,h,t,s,j)  layer-1 only
__device__ float g_asum[BH*SS];          // t-sum of layer-1 alpha (atomic)
__device__ float g_adj[BH*SS];           // pruned adj
__device__ float g_bidir2[2*H_*SS];      // (lay,h,s,j)
__device__ float g_beta[BH*S_*T_];       // (b,h,s,t)

__device__ __forceinline__ float blk_sum512(float v, float* sm){
  int tid = threadIdx.x;
  __syncthreads();
  sm[tid] = v; __syncthreads();
  #pragma unroll
  for(int s=256; s>0; s>>=1){ if(tid<s) sm[tid]+=sm[tid+s]; __syncthreads(); }
  return sm[0];
}

// ================= K0: prologue (BN+hinit | PE+cnt | bidir + zero asum) =================
__global__ void k_pro(const float* __restrict__ x, const float* __restrict__ bn_g,
                      const float* __restrict__ bn_b, const float* __restrict__ mask,
                      const float* __restrict__ times, const float* __restrict__ obs,
                      const float* __restrict__ bw){
  int blk = blockIdx.x, tid = threadIdx.x;
  if(blk < T_){
    __shared__ float sm[512];
    __shared__ float xn[B_*S_], mk[B_*S_];
    __shared__ float sc_, sh_;
    int t = blk;
    float v = 0.f;
    if(tid < B_*S_){ int b=tid/S_, s=tid%S_; v = x[(b*T_+t)*S_+s]; }
    float sum = blk_sum512(v, sm);
    float sq  = blk_sum512(v*v, sm);
    if(tid==0){
      float n=(float)(B_*S_);
      float mu=sum/n; float var=sq/n-mu*mu;
      sc_=bn_g[t]*rsqrtf(var+EPSf); sh_=bn_b[t]-mu*sc_;
    }
    __syncthreads();
    if(tid < B_*S_){
      int b=tid/S_, s=tid%S_;
      xn[tid]=v*sc_+sh_;
      mk[tid]=mask[(b*T_+t)*S_+s];
    }
    __syncthreads();
    for(int idx=tid; idx<B_*H_*S_*E_; idx+=512){
      int e  = idx & 15;
      int s  = (idx>>4)%S_;
      int hh = (idx/(16*S_))%H_;
      int b  = idx/(16*S_*H_);
      float val = xn[b*S_+s]*obs[s*(E_*H_)+hh*E_+e];
      val = LRELU(val);
      g_h[((b*H_+hh)*T_+t)*(S_*E_) + s*E_+e] = val*mk[b*S_+s];
    }
  } else if(blk == T_){
    for(int idx=tid; idx<B_*T_*PE_; idx+=512){
      int k=idx&15; int t=(idx>>4)%T_; int b=idx/(16*T_);
      float div = expf(-(float)(k>>1)*1.1512925464970229f);
      float ang = times[b*T_+t]*div;
      g_pe[idx] = (k&1) ? cosf(ang) : sinf(ang);
    }
    if(tid < B_*S_){
      int b=tid/S_, s=tid%S_;
      float c=0.f;
      #pragma unroll 4
      for(int t=0;t<T_;t++) c += mask[(b*T_+t)*S_+s];
      g_cnt[tid]=c;
    }
  } else {
    int gid = (blk - (T_+1))*512 + tid;
    for(int idx=gid; idx<2*H_*SS; idx+=8*512){
      int lay = idx/(H_*SS);
      int r   = idx%(H_*SS);
      int hh  = r/SS; int s=(r/S_)%S_; int j=r%S_;
      const float* w = bw + (size_t)(lay*H_+hh)*S_*AD_;
      float sum=0.f;
      #pragma unroll
      for(int d=0; d<AD_; d++) sum += w[s*AD_+d]*w[j*AD_+d];
      g_bidir2[idx]=LRELU(sum);
    }
    for(int idx=gid; idx<BH*SS; idx+=8*512) g_asum[idx]=0.f;
  }
}

// ================= K1: fused per-(b,h,t): hp -> alpha (-> msg if lay0; store+atomic if lay1) ====
__global__ void k_layer(const float* __restrict__ W, const float* __restrict__ pb,
                        const float* __restrict__ aw, int lay){
  __shared__ float sh_h[S_*E_];
  __shared__ float sh_hp[S_*D_];
  __shared__ float sh_W[D_*E_];
  __shared__ float sh_b[D_];
  __shared__ float sh_aw[S_*AD_];
  __shared__ float sh_pe[PE_];
  __shared__ float sh_C[S_];
  __shared__ float sh_a[SS];
  int blk = blockIdx.x, tid = threadIdx.x;
  int bh = blk/T_, t = blk%T_;
  int b = bh/H_, hh = bh%H_;
  int hbase = blk*S_*E_;
  for(int i=tid;i<S_*E_;i+=256) sh_h[i]=g_h[hbase+i];
  for(int i=tid;i<D_*E_;i+=256) sh_W[i]=W[i];
  if(tid<D_) sh_b[tid]=pb[tid];
  for(int i=tid;i<S_*AD_;i+=256) sh_aw[i]=aw[hh*S_*AD_+i];
  if(tid<PE_) sh_pe[tid]=g_pe[(b*T_+t)*PE_+tid];
  __syncthreads();
  for(int o=tid;o<S_*32;o+=256){
    int s=o>>5, d=o&31;
    if(d<D_){
      float sum=sh_b[d];
      #pragma unroll
      for(int e=0;e<E_;e++) sum += sh_h[s*E_+e]*sh_W[d*E_+e];
      sh_hp[s*D_+d]=sum;
    }
  }
  __syncthreads();
  if(tid<S_){
    float c=0.f;
    #pragma unroll
    for(int d=0;d<PE_;d++) c += sh_hp[tid*D_+AD_+d]*sh_pe[d];
    sh_C[tid]=c;
  }
  __syncthreads();
  if(lay){
    int abase = blk*SS;
    int sbase = bh*SS;
    for(int o=tid;o<SS;o+=256){
      int s=o/S_, j=o-s*S_;
      float sum=sh_C[s];
      #pragma unroll
      for(int d=0;d<AD_;d++) sum += sh_hp[s*D_+d]*sh_aw[j*AD_+d];
      float a = LRELU(sum);
      g_alpha[abase+o]=a;
      atomicAdd(&g_asum[sbase+o], a);
    }
    return;
  }
  const float* bd = g_bidir2 + hh*SS;
  for(int o=tid;o<SS;o+=256){
    int s=o/S_, j=o-s*S_;
    float sum=sh_C[s];
    #pragma unroll
    for(int d=0;d<AD_;d++) sum += sh_hp[s*D_+d]*sh_aw[j*AD_+d];
    float a = LRELU(sum);
    sh_a[o] = LRELU(bd[o]*a);
  }
  __syncthreads();
  for(int o=tid;o<S_*E_;o+=256){
    int s=o>>4, e=o&15;
    float sum=0.f;
    #pragma unroll
    for(int j=0;j<S_;j++){
      float p = sh_h[j*E_+e]*sh_a[s*S_+j];
      sum += LRELU(p);
    }
    g_h[hbase+o]=LRELU(sum);
  }
}

// ================= K2: prune — one block per (b,h,8-elem chunk): grid=BH*162 =================
__global__ void k_prune(){
  __shared__ float vals[SS];
  __shared__ float cnt[S_];
  int bh = blockIdx.x/162;
  int chunk = blockIdx.x%162;
  int tid = threadIdx.x;
  int b = bh/H_;
  if(tid<S_) cnt[tid]=g_cnt[b*S_+tid];
  __syncthreads();
  const float* src = g_asum + bh*SS;
  for(int i=tid;i<SS;i+=256){
    int s=i/S_;
    vals[i]=LRELU(src[i]/cnt[s]);
  }
  __syncthreads();
  int wid = tid>>5, lane = tid&31;
  int i = chunk*8 + wid;          // one element per warp, 8 per block
  float v = vals[i];
  int c=0;
  for(int j=lane;j<SS;j+=32){     // stride-32: bank-conflict-free
    float vj = vals[j];
    c += (vj<v) || (vj==v && j<i);
  }
  #pragma unroll
  for(int o=16;o>0;o>>=1) c += __shfl_xor_sync(0xffffffffu, c, o);
  if(lane==0) g_adj[bh*SS+i] = (c>=KEEP) ? v : 0.f;
}

// ================= K3: layer-1 message passing per (b,h,t) =================
__global__ void k_msg1(){
  __shared__ float sh_h[S_*E_];
  __shared__ float sh_w[SS];
  int blk = blockIdx.x, tid = threadIdx.x;
  int bh = blk/T_; int hh = bh%H_;
  int hbase = blk*S_*E_;
  int abase = blk*SS;
  const float* bd = g_bidir2 + (H_+hh)*SS;
  const float* ad = g_adj + bh*SS;
  for(int i=tid;i<S_*E_;i+=256) sh_h[i]=g_h[hbase+i];
  for(int o=tid;o<SS;o+=256){
    float w = bd[o]*g_alpha[abase+o]*ad[o];
    sh_w[o]=LRELU(w);
  }
  __syncthreads();
  for(int o=tid;o<S_*E_;o+=256){
    int s=o>>4, e=o&15;
    float sum=0.f;
    #pragma unroll
    for(int j=0;j<S_;j++){
      float p = sh_h[j*E_+e]*sh_w[s*S_+j];
      sum += LRELU(p);
    }
    g_h[hbase+o]=LRELU(sum);
  }
}

// ================= K4: Q,K + collapsed beta, per (b,h,s) — no g_Hc store =================
__global__ void k_beta(const float* __restrict__ Wq, const float* __restrict__ bq,
                       const float* __restrict__ Wk, const float* __restrict__ bk,
                       const float* __restrict__ Ws, const float* __restrict__ bs){
  __shared__ float Hc[T_*C_];
  __shared__ float Qs[T_*TA_];
  __shared__ float Ks[T_*TA_];
  __shared__ float wq[TA_*C_], wk[TA_*C_];
  __shared__ float bqs[TA_], bks[TA_], wss[T_], kt[TA_];
  int blk = blockIdx.x;
  int bh = blk/S_, s = blk%S_;
  int b = bh/H_;
  int tid = threadIdx.x;
  for(int o=tid;o<T_*C_;o+=blockDim.x){
    int t=o>>5, d=o&31;
    float v = (d<E_) ? g_h[(bh*T_+t)*S_*E_ + s*E_ + d]
                     : g_pe[(b*T_+t)*PE_ + (d-E_)];
    Hc[o]=v;
  }
  for(int o=tid;o<TA_*C_;o+=blockDim.x){ wq[o]=Wq[o]; wk[o]=Wk[o]; }
  if(tid<TA_){ bqs[tid]=bq[tid]; bks[tid]=bk[tid]; }
  if(tid<T_) wss[tid]=Ws[tid];
  __syncthreads();
  for(int o=tid;o<T_*TA_;o+=blockDim.x){
    int t=o/TA_, q=o-t*TA_;
    float sq_=bqs[q], sk_=bks[q];
    #pragma unroll
    for(int d=0;d<C_;d++){ float hv=Hc[t*C_+d]; sq_+=hv*wq[q*C_+d]; sk_+=hv*wk[q*C_+d]; }
    Qs[o]=sq_; Ks[o]=sk_;
  }
  __syncthreads();
  if(tid<TA_){
    float sum=0.f;
    #pragma unroll
    for(int u=0;u<T_;u++) sum += wss[u]*Ks[u*TA_+tid];
    kt[tid]=sum;
  }
  __syncthreads();
  if(tid<T_){
    float sum = bs[0];
    #pragma unroll
    for(int q=0;q<TA_;q++) sum += Qs[tid*TA_+q]*kt[q];
    g_beta[blk*T_+tid]=sum;
  }
}

// ================= K5: epilogue per (b,h) — reads g_h/g_pe directly =================
__global__ void k_final(const float* __restrict__ lnt_g, const float* __restrict__ lnt_b,
                        const float* __restrict__ Wse, const float* __restrict__ bse,
                        const float* __restrict__ lns_g, const float* __restrict__ lns_b,
                        float* __restrict__ out, int out_size){
  __shared__ float sm[512];
  __shared__ float bet[S_*T_];
  __shared__ float o1s[S_*C_];
  __shared__ float o2s[S_*OH_];
  __shared__ float mu_, rs_;
  int bh = blockIdx.x, tid = threadIdx.x;
  int b = bh/H_, hh = bh%H_;
  float s1=0.f, s2=0.f;
  for(int i=tid;i<S_*T_;i+=512){ float v=g_beta[bh*S_*T_+i]; bet[i]=v; s1+=v; s2+=v*v; }
  float sum = blk_sum512(s1, sm);
  float sq  = blk_sum512(s2, sm);
  if(tid==0){ float n=(float)(S_*T_); float mu=sum/n; float var=sq/n-mu*mu; mu_=mu; rs_=rsqrtf(var+EPSf); }
  __syncthreads();
  for(int i=tid;i<S_*T_;i+=512) bet[i]=(bet[i]-mu_)*rs_*lnt_g[i]+lnt_b[i];
  __syncthreads();
  const float* hb = g_h + (size_t)bh*T_*S_*E_;
  const float* pb_ = g_pe + (size_t)b*T_*PE_;
  for(int o=tid;o<S_*C_;o+=512){
    int s=o>>5, d=o&31;
    float sum2=0.f;
    if(d<E_){
      const float* hp_ = hb + s*E_ + d;
      #pragma unroll 4
      for(int t=0;t<T_;t++) sum2 += bet[s*T_+t]*hp_[(size_t)t*S_*E_];
    } else {
      const float* pp = pb_ + (d-E_);
      #pragma unroll 4
      for(int t=0;t<T_;t++) sum2 += bet[s*T_+t]*pp[(size_t)t*PE_];
    }
    o1s[o]=LRELU(sum2);
  }
  __syncthreads();
  float t1=0.f, t2=0.f;
  for(int o=tid;o<S_*OH_;o+=512){
    int s=o/OH_, q=o&15;
    float sum2=bse[q];
    #pragma unroll
    for(int d=0;d<C_;d++) sum2 += o1s[s*C_+d]*Wse[q*C_+d];
    float v=LRELU(sum2);
    o2s[o]=v; t1+=v; t2+=v*v;
  }
  float sum2a = blk_sum512(t1, sm);
  float sq2a  = blk_sum512(t2, sm);
  if(tid==0){ float n=(float)(S_*OH_); float mu=sum2a/n; float var=sq2a/n-mu*mu; mu_=mu; rs_=rsqrtf(var+EPSf); }
  __syncthreads();
  for(int o=tid;o<S_*OH_;o+=512){
    int s=o/OH_, q=o&15;
    float v = (o2s[o]-mu_)*rs_*lns_g[o]+lns_b[o];
    out[(b*S_+s)*(H_*OH_) + hh*OH_ + q]=v;
  }
  if(bh==0){
    float qsum=0.f, tsum=0.f;
    for(int pos=tid; pos<H_*SS; pos+=512){
      int hhh=pos/SS, sj=pos%SS;
      float ts=0.f;
      #pragma unroll
      for(int bb=0;bb<B_;bb++){
        float v = g_adj[(bb*H_+hhh)*SS+sj];
        qsum += v*v; ts += v;
      }
      tsum += ts*ts;
    }
    float Sq = blk_sum512(qsum, sm);
    float T2 = blk_sum512(tsum, sm);
    if(tid==0 && out_size > B_*S_*H_*OH_)
      out[B_*S_*H_*OH_] = ((float)B_*Sq - T2) / (float)((B_-1)*(B_-1)) / (float)SS;
  }
}

// ---------------- launcher ----------------
extern "C" void kernel_launch(void* const* d_in, const int* in_sizes, int n_in,
                              void* d_out, int out_size){
  const float* x      = (const float*)d_in[0];
  const float* times  = (const float*)d_in[1];
  const float* mask   = (const float*)d_in[2];
  const float* bn_g   = (const float*)d_in[3];
  const float* bn_b   = (const float*)d_in[4];
  const float* obs    = (const float*)d_in[5];
  const float* attn_w = (const float*)d_in[6];
  const float* bidir_w= (const float*)d_in[7];
  const float* proj_W = (const float*)d_in[8];
  const float* proj_b = (const float*)d_in[9];
  const float* Wq     = (const float*)d_in[10];
  const float* bq     = (const float*)d_in[11];
  const float* Wk     = (const float*)d_in[12];
  const float* bk     = (const float*)d_in[13];
  const float* Ws     = (const float*)d_in[14];
  const float* bs     = (const float*)d_in[15];
  const float* lnt_g  = (const float*)d_in[16];
  const float* lnt_b  = (const float*)d_in[17];
  const float* Wse    = (const float*)d_in[18];
  const float* bse    = (const float*)d_in[19];
  const float* lns_g  = (const float*)d_in[20];
  const float* lns_b  = (const float*)d_in[21];
  float* out = (float*)d_out;

  k_pro<<<T_+1+8, 512>>>(x, bn_g, bn_b, mask, times, obs, bidir_w);
  k_layer<<<BH*T_, 256>>>(proj_W, proj_b, attn_w, 0);
  k_layer<<<BH*T_, 256>>>(proj_W, proj_b, attn_w + (size_t)H_*S_*AD_, 1);
  k_prune<<<BH*162, 256>>>();
  k_msg1<<<BH*T_, 256>>>();
  k_beta<<<BH*S_, 256>>>(Wq, bq, Wk, bk, Ws, bs);
  k_final<<<BH, 512>>>(lnt_g, lnt_b, Wse, bse, lns_g, lns_b, out, out_size);
}

// round 10
// speedup vs baseline: 1.2576x; 1.2576x over previous
#include <cuda_runtime.h>

#define LRELU(v) ((v) >= 0.f ? (v) : 0.01f*(v))

constexpr int B_=8, T_=60, S_=36, H_=4, E_=16, PE_=16, AD_=12, D_=28, TA_=10, C_=32, OH_=16;
constexpr int BH = B_*H_;         // 32
constexpr int SS = S_*S_;         // 1296
constexpr int KEEP = 648;         // floor(S*S*0.5)
constexpr float EPSf = 1e-5f;

// ---------------- device scratch ----------------
__device__ float g_pe[B_*T_*PE_];
__device__ float g_cnt[B_*S_];
__device__ float g_h[BH*T_*S_*E_];       // (b,h,t,s,e)
__device__ float g_alpha[BH*T_*SS];      // (b,h,t,s,j): layer-1, premultiplied by bidir
__device__ float g_asum[BH*SS];          // t-sum of layer-1 alpha (atomic)
__device__ float g_adj[BH*SS];           // pruned adj
__device__ float g_bidir2[2*H_*SS];      // (lay,h,s,j)
__device__ float g_Hc[BH*S_*T_*C_];      // (b,h,s,t,d)
__device__ float g_beta[BH*S_*T_];       // (b,h,s,t)

__device__ __forceinline__ float blk_sum512(float v, float* sm){
  int tid = threadIdx.x;
  __syncthreads();
  sm[tid] = v; __syncthreads();
  #pragma unroll
  for(int s=256; s>0; s>>=1){ if(tid<s) sm[tid]+=sm[tid+s]; __syncthreads(); }
  return sm[0];
}

// ================= K0: prologue (BN+hinit | PE+cnt | bidir + zero asum) =================
__global__ void k_pro(const float* __restrict__ x, const float* __restrict__ bn_g,
                      const float* __restrict__ bn_b, const float* __restrict__ mask,
                      const float* __restrict__ times, const float* __restrict__ obs,
                      const float* __restrict__ bw){
  int blk = blockIdx.x, tid = threadIdx.x;
  if(blk < T_){
    __shared__ float sm[512];
    __shared__ float xn[B_*S_], mk[B_*S_];
    __shared__ float sc_, sh_;
    int t = blk;
    float v = 0.f;
    if(tid < B_*S_){ int b=tid/S_, s=tid%S_; v = x[(b*T_+t)*S_+s]; }
    float sum = blk_sum512(v, sm);
    float sq  = blk_sum512(v*v, sm);
    if(tid==0){
      float n=(float)(B_*S_);
      float mu=sum/n; float var=sq/n-mu*mu;
      sc_=bn_g[t]*rsqrtf(var+EPSf); sh_=bn_b[t]-mu*sc_;
    }
    __syncthreads();
    if(tid < B_*S_){
      int b=tid/S_, s=tid%S_;
      xn[tid]=v*sc_+sh_;
      mk[tid]=mask[(b*T_+t)*S_+s];
    }
    __syncthreads();
    for(int idx=tid; idx<B_*H_*S_*E_; idx+=512){
      int e  = idx & 15;
      int s  = (idx>>4)%S_;
      int hh = (idx/(16*S_))%H_;
      int b  = idx/(16*S_*H_);
      float val = xn[b*S_+s]*obs[s*(E_*H_)+hh*E_+e];
      val = LRELU(val);
      g_h[((b*H_+hh)*T_+t)*(S_*E_) + s*E_+e] = val*mk[b*S_+s];
    }
  } else if(blk == T_){
    for(int idx=tid; idx<B_*T_*PE_; idx+=512){
      int k=idx&15; int t=(idx>>4)%T_; int b=idx/(16*T_);
      float div = expf(-(float)(k>>1)*1.1512925464970229f);
      float ang = times[b*T_+t]*div;
      g_pe[idx] = (k&1) ? cosf(ang) : sinf(ang);
    }
    if(tid < B_*S_){
      int b=tid/S_, s=tid%S_;
      float c=0.f;
      #pragma unroll 4
      for(int t=0;t<T_;t++) c += mask[(b*T_+t)*S_+s];
      g_cnt[tid]=c;
    }
  } else {
    int gid = (blk - (T_+1))*512 + tid;
    for(int idx=gid; idx<2*H_*SS; idx+=8*512){
      int lay = idx/(H_*SS);
      int r   = idx%(H_*SS);
      int hh  = r/SS; int s=(r/S_)%S_; int j=r%S_;
      const float* w = bw + (size_t)(lay*H_+hh)*S_*AD_;
      float sum=0.f;
      #pragma unroll
      for(int d=0; d<AD_; d++) sum += w[s*AD_+d]*w[j*AD_+d];
      g_bidir2[idx]=LRELU(sum);
    }
    for(int idx=gid; idx<BH*SS; idx+=8*512) g_asum[idx]=0.f;
  }
}

// ================= K1: fused per-(b,h,t): hp -> alpha (-> msg if lay0; store+atomic if lay1) ====
__global__ void k_layer(const float* __restrict__ W, const float* __restrict__ pb,
                        const float* __restrict__ aw, int lay){
  __shared__ float sh_h[S_*E_];
  __shared__ float sh_hp[S_*D_];
  __shared__ float sh_W[D_*E_];
  __shared__ float sh_b[D_];
  __shared__ float sh_aw[S_*AD_];
  __shared__ float sh_pe[PE_];
  __shared__ float sh_C[S_];
  __shared__ float sh_a[SS];
  int blk = blockIdx.x, tid = threadIdx.x;
  int bh = blk/T_, t = blk%T_;
  int b = bh/H_, hh = bh%H_;
  int hbase = blk*S_*E_;
  for(int i=tid;i<S_*E_;i+=256) sh_h[i]=g_h[hbase+i];
  for(int i=tid;i<D_*E_;i+=256) sh_W[i]=W[i];
  if(tid<D_) sh_b[tid]=pb[tid];
  for(int i=tid;i<S_*AD_;i+=256) sh_aw[i]=aw[hh*S_*AD_+i];
  if(tid<PE_) sh_pe[tid]=g_pe[(b*T_+t)*PE_+tid];
  __syncthreads();
  for(int o=tid;o<S_*32;o+=256){
    int s=o>>5, d=o&31;
    if(d<D_){
      float sum=sh_b[d];
      #pragma unroll
      for(int e=0;e<E_;e++) sum += sh_h[s*E_+e]*sh_W[d*E_+e];
      sh_hp[s*D_+d]=sum;
    }
  }
  __syncthreads();
  if(tid<S_){
    float c=0.f;
    #pragma unroll
    for(int d=0;d<PE_;d++) c += sh_hp[tid*D_+AD_+d]*sh_pe[d];
    sh_C[tid]=c;
  }
  __syncthreads();
  if(lay){
    int abase = blk*SS;
    int sbase = bh*SS;
    const float* bd1 = g_bidir2 + (H_+hh)*SS;
    // 4-j blocked: unit u -> s=u/9, j0=(u%9)*4
    for(int u=tid;u<S_*9;u+=256){
      int s=u/9, j0=(u-s*9)*4;
      float hp[AD_];
      #pragma unroll
      for(int d=0;d<AD_;d++) hp[d]=sh_hp[s*D_+d];
      float base=sh_C[s];
      float a[4];
      #pragma unroll
      for(int jj=0;jj<4;jj++){
        int j=j0+jj;
        float sum=base;
        #pragma unroll
        for(int d=0;d<AD_;d++) sum += hp[d]*sh_aw[j*AD_+d];
        a[jj]=LRELU(sum);
      }
      int o = s*S_+j0;
      float4 st;
      st.x = bd1[o  ]*a[0];
      st.y = bd1[o+1]*a[1];
      st.z = bd1[o+2]*a[2];
      st.w = bd1[o+3]*a[3];
      *reinterpret_cast<float4*>(&g_alpha[abase+o]) = st;
      atomicAdd(&g_asum[sbase+o  ], a[0]);
      atomicAdd(&g_asum[sbase+o+1], a[1]);
      atomicAdd(&g_asum[sbase+o+2], a[2]);
      atomicAdd(&g_asum[sbase+o+3], a[3]);
    }
    return;
  }
  const float* bd = g_bidir2 + hh*SS;
  for(int u=tid;u<S_*9;u+=256){
    int s=u/9, j0=(u-s*9)*4;
    float hp[AD_];
    #pragma unroll
    for(int d=0;d<AD_;d++) hp[d]=sh_hp[s*D_+d];
    float base=sh_C[s];
    #pragma unroll
    for(int jj=0;jj<4;jj++){
      int j=j0+jj;
      float sum=base;
      #pragma unroll
      for(int d=0;d<AD_;d++) sum += hp[d]*sh_aw[j*AD_+d];
      float a = LRELU(sum);
      int o = s*S_+j;
      sh_a[o] = LRELU(bd[o]*a);
    }
  }
  __syncthreads();
  // msg: 2-e blocked, float2 store
  for(int u=tid;u<S_*8;u+=256){
    int s=u>>3, ep=(u&7)*2;
    float sum0=0.f, sum1=0.f;
    #pragma unroll
    for(int j=0;j<S_;j++){
      float wv = sh_a[s*S_+j];
      float p0 = sh_h[j*E_+ep  ]*wv;
      float p1 = sh_h[j*E_+ep+1]*wv;
      sum0 += LRELU(p0);
      sum1 += LRELU(p1);
    }
    float2 st; st.x=LRELU(sum0); st.y=LRELU(sum1);
    *reinterpret_cast<float2*>(&g_h[hbase + s*E_ + ep]) = st;
  }
}

// ================= K2: prune — one block per (b,h,row): grid=BH*36 (measured-best config) ======
__global__ void k_prune(){
  __shared__ float vals[SS];
  __shared__ float cnt[S_];
  int bh = blockIdx.x/S_;
  int row = blockIdx.x%S_;
  int tid = threadIdx.x;
  int b = bh/H_;
  if(tid<S_) cnt[tid]=g_cnt[b*S_+tid];
  __syncthreads();
  const float* src = g_asum + bh*SS;
  for(int i=tid;i<SS;i+=256){
    int s=i/S_;
    vals[i]=LRELU(src[i]/cnt[s]);
  }
  __syncthreads();
  int wid = tid>>5, lane = tid&31;
  float* dst = g_adj + bh*SS;
  // 8 warps cover the 36 elements of this row; stride-32 scalar = conflict-free
  for(int e=wid; e<S_; e+=8){
    int i = row*S_ + e;
    float v = vals[i];
    int c=0;
    for(int j=lane;j<SS;j+=32){
      float vj = vals[j];
      c += (vj<v) || (vj==v && j<i);
    }
    #pragma unroll
    for(int o=16;o>0;o>>=1) c += __shfl_xor_sync(0xffffffffu, c, o);
    if(lane==0) dst[i] = (c>=KEEP) ? v : 0.f;
  }
}

// ================= K3: layer-1 message passing per (b,h,t) (alpha premultiplied by bidir) =====
__global__ void k_msg1(){
  __shared__ float sh_h[S_*E_];
  __shared__ float sh_w[SS];
  int blk = blockIdx.x, tid = threadIdx.x;
  int bh = blk/T_;
  int hbase = blk*S_*E_;
  int abase = blk*SS;
  const float* ad = g_adj + bh*SS;
  for(int i=tid;i<S_*E_;i+=256) sh_h[i]=g_h[hbase+i];
  for(int o=tid;o<SS;o+=256){
    float w = g_alpha[abase+o]*ad[o];   // g_alpha already = bidir*alpha
    sh_w[o]=LRELU(w);
  }
  __syncthreads();
  for(int u=tid;u<S_*8;u+=256){
    int s=u>>3, ep=(u&7)*2;
    float sum0=0.f, sum1=0.f;
    #pragma unroll
    for(int j=0;j<S_;j++){
      float wv = sh_w[s*S_+j];
      float p0 = sh_h[j*E_+ep  ]*wv;
      float p1 = sh_h[j*E_+ep+1]*wv;
      sum0 += LRELU(p0);
      sum1 += LRELU(p1);
    }
    float2 st; st.x=LRELU(sum0); st.y=LRELU(sum1);
    *reinterpret_cast<float2*>(&g_h[hbase + s*E_ + ep]) = st;
  }
}

// ================= K4: Hc + Q,K + collapsed beta, per (b,h,s) =================
__global__ void k_beta(const float* __restrict__ Wq, const float* __restrict__ bq,
                       const float* __restrict__ Wk, const float* __restrict__ bk,
                       const float* __restrict__ Ws, const float* __restrict__ bs){
  __shared__ float Hc[T_*C_];
  __shared__ float Qs[T_*TA_];
  __shared__ float Ks[T_*TA_];
  __shared__ float wq[TA_*C_], wk[TA_*C_];
  __shared__ float bqs[TA_], bks[TA_], wss[T_], kt[TA_];
  int blk = blockIdx.x;
  int bh = blk/S_, s = blk%S_;
  int b = bh/H_;
  int tid = threadIdx.x;
  for(int o=tid;o<T_*C_;o+=blockDim.x){
    int t=o>>5, d=o&31;
    float v = (d<E_) ? g_h[(bh*T_+t)*S_*E_ + s*E_ + d]
                     : g_pe[(b*T_+t)*PE_ + (d-E_)];
    Hc[o]=v;
    g_Hc[blk*T_*C_+o]=v;
  }
  for(int o=tid;o<TA_*C_;o+=blockDim.x){ wq[o]=Wq[o]; wk[o]=Wk[o]; }
  if(tid<TA_){ bqs[tid]=bq[tid]; bks[tid]=bk[tid]; }
  if(tid<T_) wss[tid]=Ws[tid];
  __syncthreads();
  for(int o=tid;o<T_*TA_;o+=blockDim.x){
    int t=o/TA_, q=o-t*TA_;
    float sq_=bqs[q], sk_=bks[q];
    #pragma unroll
    for(int d=0;d<C_;d++){ float hv=Hc[t*C_+d]; sq_+=hv*wq[q*C_+d]; sk_+=hv*wk[q*C_+d]; }
    Qs[o]=sq_; Ks[o]=sk_;
  }
  __syncthreads();
  if(tid<TA_){
    float sum=0.f;
    #pragma unroll
    for(int u=0;u<T_;u++) sum += wss[u]*Ks[u*TA_+tid];
    kt[tid]=sum;
  }
  __syncthreads();
  if(tid<T_){
    float sum = bs[0];
    #pragma unroll
    for(int q=0;q<TA_;q++) sum += Qs[tid*TA_+q]*kt[q];
    g_beta[blk*T_+tid]=sum;
  }
}

// ================= K5: epilogue per (b,h) =================
__global__ void k_final(const float* __restrict__ lnt_g, const float* __restrict__ lnt_b,
                        const float* __restrict__ Wse, const float* __restrict__ bse,
                        const float* __restrict__ lns_g, const float* __restrict__ lns_b,
                        float* __restrict__ out, int out_size){
  __shared__ float sm[512];
  __shared__ float bet[S_*T_];
  __shared__ float o1s[S_*C_];
  __shared__ float o2s[S_*OH_];
  __shared__ float mu_, rs_;
  int bh = blockIdx.x, tid = threadIdx.x;
  int b = bh/H_, hh = bh%H_;
  float s1=0.f, s2=0.f;
  for(int i=tid;i<S_*T_;i+=512){ float v=g_beta[bh*S_*T_+i]; bet[i]=v; s1+=v; s2+=v*v; }
  float sum = blk_sum512(s1, sm);
  float sq  = blk_sum512(s2, sm);
  if(tid==0){ float n=(float)(S_*T_); float mu=sum/n; float var=sq/n-mu*mu; mu_=mu; rs_=rsqrtf(var+EPSf); }
  __syncthreads();
  for(int i=tid;i<S_*T_;i+=512) bet[i]=(bet[i]-mu_)*rs_*lnt_g[i]+lnt_b[i];
  __syncthreads();
  for(int o=tid;o<S_*C_;o+=512){
    int s=o>>5, d=o&31;
    const float* hc = g_Hc + ((size_t)(bh*S_+s)*T_)*C_ + d;
    float sum2=0.f;
    #pragma unroll 4
    for(int t=0;t<T_;t++) sum2 += bet[s*T_+t]*hc[(size_t)t*C_];
    o1s[o]=LRELU(sum2);
  }
  __syncthreads();
  float t1=0.f, t2=0.f;
  for(int o=tid;o<S_*OH_;o+=512){
    int s=o/OH_, q=o&15;
    float sum2=bse[q];
    #pragma unroll
    for(int d=0;d<C_;d++) sum2 += o1s[s*C_+d]*Wse[q*C_+d];
    float v=LRELU(sum2);
    o2s[o]=v; t1+=v; t2+=v*v;
  }
  float sum2a = blk_sum512(t1, sm);
  float sq2a  = blk_sum512(t2, sm);
  if(tid==0){ float n=(float)(S_*OH_); float mu=sum2a/n; float var=sq2a/n-mu*mu; mu_=mu; rs_=rsqrtf(var+EPSf); }
  __syncthreads();
  for(int o=tid;o<S_*OH_;o+=512){
    int s=o/OH_, q=o&15;
    float v = (o2s[o]-mu_)*rs_*lns_g[o]+lns_b[o];
    out[(b*S_+s)*(H_*OH_) + hh*OH_ + q]=v;
  }
  if(bh==0){
    float qsum=0.f, tsum=0.f;
    for(int pos=tid; pos<H_*SS; pos+=512){
      int hhh=pos/SS, sj=pos%SS;
      float ts=0.f;
      #pragma unroll
      for(int bb=0;bb<B_;bb++){
        float v = g_adj[(bb*H_+hhh)*SS+sj];
        qsum += v*v; ts += v;
      }
      tsum += ts*ts;
    }
    float Sq = blk_sum512(qsum, sm);
    float T2 = blk_sum512(tsum, sm);
    if(tid==0 && out_size > B_*S_*H_*OH_)
      out[B_*S_*H_*OH_] = ((float)B_*Sq - T2) / (float)((B_-1)*(B_-1)) / (float)SS;
  }
}

// ---------------- launcher ----------------
extern "C" void kernel_launch(void* const* d_in, const int* in_sizes, int n_in,
                              void* d_out, int out_size){
  const float* x      = (const float*)d_in[0];
  const float* times  = (const float*)d_in[1];
  const float* mask   = (const float*)d_in[2];
  const float* bn_g   = (const float*)d_in[3];
  const float* bn_b   = (const float*)d_in[4];
  const float* obs    = (const float*)d_in[5];
  const float* attn_w = (const float*)d_in[6];
  const float* bidir_w= (const float*)d_in[7];
  const float* proj_W = (const float*)d_in[8];
  const float* proj_b = (const float*)d_in[9];
  const float* Wq     = (const float*)d_in[10];
  const float* bq     = (const float*)d_in[11];
  const float* Wk     = (const float*)d_in[12];
  const float* bk     = (const float*)d_in[13];
  const float* Ws     = (const float*)d_in[14];
  const float* bs     = (const float*)d_in[15];
  const float* lnt_g  = (const float*)d_in[16];
  const float* lnt_b  = (const float*)d_in[17];
  const float* Wse    = (const float*)d_in[18];
  const float* bse    = (const float*)d_in[19];
  const float* lns_g  = (const float*)d_in[20];
  const float* lns_b  = (const float*)d_in[21];
  float* out = (float*)d_out;

  k_pro<<<T_+1+8, 512>>>(x, bn_g, bn_b, mask, times, obs, bidir_w);
  k_layer<<<BH*T_, 256>>>(proj_W, proj_b, attn_w, 0);
  k_layer<<<BH*T_, 256>>>(proj_W, proj_b, attn_w + (size_t)H_*S_*AD_, 1);
  k_prune<<<BH*S_, 256>>>();
  k_msg1<<<BH*T_, 256>>>();
  k_beta<<<BH*S_, 256>>>(Wq, bq, Wk, bk, Ws, bs);
  k_final<<<BH, 512>>>(lnt_g, lnt_b, Wse, bse, lns_g, lns_b, out, out_size);
}

// round 11
// speedup vs baseline: 1.6094x; 1.2797x over previous
#include <cuda_runtime.h>

#define LRELU(v) ((v) >= 0.f ? (v) : 0.01f*(v))

constexpr int B_=8, T_=60, S_=36, H_=4, E_=16, PE_=16, AD_=12, D_=28, TA_=10, C_=32, OH_=16;
constexpr int BH = B_*H_;         // 32
constexpr int SS = S_*S_;         // 1296
constexpr int KEEP = 648;         // floor(S*S*0.5)
constexpr float EPSf = 1e-5f;

// ---------------- device scratch ----------------
__device__ float g_pe[B_*T_*PE_];
__device__ float g_rcnt[B_*S_];          // 1/cnt
__device__ float g_h[BH*T_*S_*E_];       // (b,h,t,s,e)
__device__ float g_alpha[BH*T_*SS];      // (b,h,t,s,j)  layer-1 only
__device__ float g_asum[BH*SS];          // t-sum of layer-1 alpha (atomic)
__device__ float g_adj[BH*SS];           // pruned adj
__device__ float g_bidir2[2*H_*SS];      // (lay,h,s,j)
__device__ float g_Hc[BH*S_*T_*C_];      // (b,h,s,t,d)
__device__ float g_beta[BH*S_*T_];       // (b,h,s,t)

__device__ __forceinline__ float blk_sum512(float v, float* sm){
  int tid = threadIdx.x;
  __syncthreads();
  sm[tid] = v; __syncthreads();
  #pragma unroll
  for(int s=256; s>0; s>>=1){ if(tid<s) sm[tid]+=sm[tid+s]; __syncthreads(); }
  return sm[0];
}

// ================= K0: prologue (BN+hinit | PE+rcnt | bidir + zero asum) =================
__global__ void k_pro(const float* __restrict__ x, const float* __restrict__ bn_g,
                      const float* __restrict__ bn_b, const float* __restrict__ mask,
                      const float* __restrict__ times, const float* __restrict__ obs,
                      const float* __restrict__ bw){
  int blk = blockIdx.x, tid = threadIdx.x;
  if(blk < T_){
    __shared__ float sm[512];
    __shared__ float xn[B_*S_], mk[B_*S_];
    __shared__ float sc_, sh_;
    int t = blk;
    float v = 0.f;
    if(tid < B_*S_){ int b=tid/S_, s=tid%S_; v = x[(b*T_+t)*S_+s]; }
    float sum = blk_sum512(v, sm);
    float sq  = blk_sum512(v*v, sm);
    if(tid==0){
      float n=(float)(B_*S_);
      float mu=sum/n; float var=sq/n-mu*mu;
      sc_=bn_g[t]*rsqrtf(var+EPSf); sh_=bn_b[t]-mu*sc_;
    }
    __syncthreads();
    if(tid < B_*S_){
      int b=tid/S_, s=tid%S_;
      xn[tid]=v*sc_+sh_;
      mk[tid]=mask[(b*T_+t)*S_+s];
    }
    __syncthreads();
    for(int idx=tid; idx<B_*H_*S_*E_; idx+=512){
      int e  = idx & 15;
      int s  = (idx>>4)%S_;
      int hh = (idx/(16*S_))%H_;
      int b  = idx/(16*S_*H_);
      float val = xn[b*S_+s]*obs[s*(E_*H_)+hh*E_+e];
      val = LRELU(val);
      g_h[((b*H_+hh)*T_+t)*(S_*E_) + s*E_+e] = val*mk[b*S_+s];
    }
  } else if(blk == T_){
    for(int idx=tid; idx<B_*T_*PE_; idx+=512){
      int k=idx&15; int t=(idx>>4)%T_; int b=idx/(16*T_);
      float div = expf(-(float)(k>>1)*1.1512925464970229f);
      float ang = times[b*T_+t]*div;
      g_pe[idx] = (k&1) ? cosf(ang) : sinf(ang);
    }
    if(tid < B_*S_){
      int b=tid/S_, s=tid%S_;
      float c=0.f;
      #pragma unroll 4
      for(int t=0;t<T_;t++) c += mask[(b*T_+t)*S_+s];
      g_rcnt[tid]=1.0f/c;
    }
  } else {
    int gid = (blk - (T_+1))*512 + tid;
    for(int idx=gid; idx<2*H_*SS; idx+=8*512){
      int lay = idx/(H_*SS);
      int r   = idx%(H_*SS);
      int hh  = r/SS; int s=(r/S_)%S_; int j=r%S_;
      const float* w = bw + (size_t)(lay*H_+hh)*S_*AD_;
      float sum=0.f;
      #pragma unroll
      for(int d=0; d<AD_; d++) sum += w[s*AD_+d]*w[j*AD_+d];
      g_bidir2[idx]=LRELU(sum);
    }
    for(int idx=gid; idx<BH*SS; idx+=8*512) g_asum[idx]=0.f;
  }
}

// ================= K1: fused per-(b,h,t): hp -> alpha (-> msg if lay0; store+atomic if lay1) ====
__global__ void k_layer(const float* __restrict__ W, const float* __restrict__ pb,
                        const float* __restrict__ aw, int lay){
  __shared__ float sh_h[S_*E_];
  __shared__ float sh_hp[S_*D_];
  __shared__ float sh_W[D_*E_];
  __shared__ float sh_b[D_];
  __shared__ float sh_aw[S_*AD_];
  __shared__ float sh_pe[PE_];
  __shared__ float sh_C[S_];
  __shared__ float sh_a[SS];
  int blk = blockIdx.x, tid = threadIdx.x;
  int bh = blk/T_, t = blk%T_;
  int b = bh/H_, hh = bh%H_;
  int hbase = blk*S_*E_;
  for(int i=tid;i<S_*E_;i+=256) sh_h[i]=g_h[hbase+i];
  for(int i=tid;i<D_*E_;i+=256) sh_W[i]=W[i];
  if(tid<D_) sh_b[tid]=pb[tid];
  for(int i=tid;i<S_*AD_;i+=256) sh_aw[i]=aw[hh*S_*AD_+i];
  if(tid<PE_) sh_pe[tid]=g_pe[(b*T_+t)*PE_+tid];
  __syncthreads();
  for(int o=tid;o<S_*32;o+=256){
    int s=o>>5, d=o&31;
    if(d<D_){
      float sum=sh_b[d];
      #pragma unroll
      for(int e=0;e<E_;e++) sum += sh_h[s*E_+e]*sh_W[d*E_+e];
      sh_hp[s*D_+d]=sum;
    }
  }
  __syncthreads();
  if(tid<S_){
    float c=0.f;
    #pragma unroll
    for(int d=0;d<PE_;d++) c += sh_hp[tid*D_+AD_+d]*sh_pe[d];
    sh_C[tid]=c;
  }
  __syncthreads();
  if(lay){
    int abase = blk*SS;
    int sbase = bh*SS;
    for(int o=tid;o<SS;o+=256){
      int s=o/S_, j=o-s*S_;
      float sum=sh_C[s];
      #pragma unroll
      for(int d=0;d<AD_;d++) sum += sh_hp[s*D_+d]*sh_aw[j*AD_+d];
      float a = LRELU(sum);
      g_alpha[abase+o]=a;
      atomicAdd(&g_asum[sbase+o], a);
    }
    return;
  }
  const float* bd = g_bidir2 + hh*SS;
  for(int o=tid;o<SS;o+=256){
    int s=o/S_, j=o-s*S_;
    float sum=sh_C[s];
    #pragma unroll
    for(int d=0;d<AD_;d++) sum += sh_hp[s*D_+d]*sh_aw[j*AD_+d];
    float a = LRELU(sum);
    sh_a[o] = LRELU(bd[o]*a);
  }
  __syncthreads();
  for(int o=tid;o<S_*E_;o+=256){
    int s=o>>4, e=o&15;
    float sum=0.f;
    #pragma unroll
    for(int j=0;j<S_;j++){
      float p = sh_h[j*E_+e]*sh_a[s*S_+j];
      sum += LRELU(p);
    }
    g_h[hbase+o]=LRELU(sum);
  }
}

// ================= K2: prune — one block per (b,h,row): grid=BH*36 =================
__global__ void k_prune(){
  __shared__ float vals[SS];
  __shared__ float rcnt[S_];
  int bh = blockIdx.x/S_;
  int row = blockIdx.x%S_;
  int tid = threadIdx.x;
  int b = bh/H_;
  if(tid<S_) rcnt[tid]=g_rcnt[b*S_+tid];
  __syncthreads();
  const float* src = g_asum + bh*SS;
  for(int i=tid;i<SS;i+=256){
    int s=i/S_;
    vals[i]=LRELU(src[i]*rcnt[s]);
  }
  __syncthreads();
  int wid = tid>>5, lane = tid&31;
  float* dst = g_adj + bh*SS;
  // 8 warps cover the 36 elements of this row; stride-32 scalar = conflict-free
  for(int e=wid; e<S_; e+=8){
    int i = row*S_ + e;
    float v = vals[i];
    int c=0;
    for(int j=lane;j<SS;j+=32){
      float vj = vals[j];
      c += (vj<v) || (vj==v && j<i);
    }
    #pragma unroll
    for(int o=16;o>0;o>>=1) c += __shfl_xor_sync(0xffffffffu, c, o);
    if(lane==0) dst[i] = (c>=KEEP) ? v : 0.f;
  }
}

// ================= K3: layer-1 message passing per (b,h,t) =================
__global__ void k_msg1(){
  __shared__ float sh_h[S_*E_];
  __shared__ float sh_w[SS];
  int blk = blockIdx.x, tid = threadIdx.x;
  int bh = blk/T_; int hh = bh%H_;
  int hbase = blk*S_*E_;
  int abase = blk*SS;
  const float* bd = g_bidir2 + (H_+hh)*SS;
  const float* ad = g_adj + bh*SS;
  for(int i=tid;i<S_*E_;i+=256) sh_h[i]=g_h[hbase+i];
  for(int o=tid;o<SS;o+=256){
    float w = bd[o]*g_alpha[abase+o]*ad[o];
    sh_w[o]=LRELU(w);
  }
  __syncthreads();
  for(int o=tid;o<S_*E_;o+=256){
    int s=o>>4, e=o&15;
    float sum=0.f;
    #pragma unroll
    for(int j=0;j<S_;j++){
      float p = sh_h[j*E_+e]*sh_w[s*S_+j];
      sum += LRELU(p);
    }
    g_h[hbase+o]=LRELU(sum);
  }
}

// ================= K4: Hc + Q,K + collapsed beta, per (b,h,s) =================
__global__ void k_beta(const float* __restrict__ Wq, const float* __restrict__ bq,
                       const float* __restrict__ Wk, const float* __restrict__ bk,
                       const float* __restrict__ Ws, const float* __restrict__ bs){
  __shared__ float Hc[T_*C_];
  __shared__ float Qs[T_*TA_];
  __shared__ float Ks[T_*TA_];
  __shared__ float wq[TA_*C_], wk[TA_*C_];
  __shared__ float bqs[TA_], bks[TA_], wss[T_], kt[TA_];
  int blk = blockIdx.x;
  int bh = blk/S_, s = blk%S_;
  int b = bh/H_;
  int tid = threadIdx.x;
  for(int o=tid;o<T_*C_;o+=blockDim.x){
    int t=o>>5, d=o&31;
    float v = (d<E_) ? g_h[(bh*T_+t)*S_*E_ + s*E_ + d]
                     : g_pe[(b*T_+t)*PE_ + (d-E_)];
    Hc[o]=v;
    g_Hc[blk*T_*C_+o]=v;
  }
  for(int o=tid;o<TA_*C_;o+=blockDim.x){ wq[o]=Wq[o]; wk[o]=Wk[o]; }
  if(tid<TA_){ bqs[tid]=bq[tid]; bks[tid]=bk[tid]; }
  if(tid<T_) wss[tid]=Ws[tid];
  __syncthreads();
  for(int o=tid;o<T_*TA_;o+=blockDim.x){
    int t=o/TA_, q=o-t*TA_;
    float sq_=bqs[q], sk_=bks[q];
    #pragma unroll
    for(int d=0;d<C_;d++){ float hv=Hc[t*C_+d]; sq_+=hv*wq[q*C_+d]; sk_+=hv*wk[q*C_+d]; }
    Qs[o]=sq_; Ks[o]=sk_;
  }
  __syncthreads();
  if(tid<TA_){
    float sum=0.f;
    #pragma unroll
    for(int u=0;u<T_;u++) sum += wss[u]*Ks[u*TA_+tid];
    kt[tid]=sum;
  }
  __syncthreads();
  if(tid<T_){
    float sum = bs[0];
    #pragma unroll
    for(int q=0;q<TA_;q++) sum += Qs[tid*TA_+q]*kt[q];
    g_beta[blk*T_+tid]=sum;
  }
}

// ================= K5: epilogue per (b,h) =================
__global__ void k_final(const float* __restrict__ lnt_g, const float* __restrict__ lnt_b,
                        const float* __restrict__ Wse, const float* __restrict__ bse,
                        const float* __restrict__ lns_g, const float* __restrict__ lns_b,
                        float* __restrict__ out, int out_size){
  __shared__ float sm[512];
  __shared__ float bet[S_*T_];
  __shared__ float o1s[S_*C_];
  __shared__ float o2s[S_*OH_];
  __shared__ float mu_, rs_;
  int bh = blockIdx.x, tid = threadIdx.x;
  int b = bh/H_, hh = bh%H_;
  float s1=0.f, s2=0.f;
  for(int i=tid;i<S_*T_;i+=512){ float v=g_beta[bh*S_*T_+i]; bet[i]=v; s1+=v; s2+=v*v; }
  float sum = blk_sum512(s1, sm);
  float sq  = blk_sum512(s2, sm);
  if(tid==0){ float n=(float)(S_*T_); float mu=sum/n; float var=sq/n-mu*mu; mu_=mu; rs_=rsqrtf(var+EPSf); }
  __syncthreads();
  for(int i=tid;i<S_*T_;i+=512) bet[i]=(bet[i]-mu_)*rs_*lnt_g[i]+lnt_b[i];
  __syncthreads();
  for(int o=tid;o<S_*C_;o+=512){
    int s=o>>5, d=o&31;
    const float* hc = g_Hc + ((size_t)(bh*S_+s)*T_)*C_ + d;
    float sum2=0.f;
    #pragma unroll 4
    for(int t=0;t<T_;t++) sum2 += bet[s*T_+t]*hc[(size_t)t*C_];
    o1s[o]=LRELU(sum2);
  }
  __syncthreads();
  float t1=0.f, t2=0.f;
  for(int o=tid;o<S_*OH_;o+=512){
    int s=o/OH_, q=o&15;
    float sum2=bse[q];
    #pragma unroll
    for(int d=0;d<C_;d++) sum2 += o1s[s*C_+d]*Wse[q*C_+d];
    float v=LRELU(sum2);
    o2s[o]=v; t1+=v; t2+=v*v;
  }
  float sum2a = blk_sum512(t1, sm);
  float sq2a  = blk_sum512(t2, sm);
  if(tid==0){ float n=(float)(S_*OH_); float mu=sum2a/n; float var=sq2a/n-mu*mu; mu_=mu; rs_=rsqrtf(var+EPSf); }
  __syncthreads();
  for(int o=tid;o<S_*OH_;o+=512){
    int s=o/OH_, q=o&15;
    float v = (o2s[o]-mu_)*rs_*lns_g[o]+lns_b[o];
    out[(b*S_+s)*(H_*OH_) + hh*OH_ + q]=v;
  }
  if(bh==0){
    float qsum=0.f, tsum=0.f;
    for(int pos=tid; pos<H_*SS; pos+=512){
      int hhh=pos/SS, sj=pos%SS;
      float ts=0.f;
      #pragma unroll
      for(int bb=0;bb<B_;bb++){
        float v = g_adj[(bb*H_+hhh)*SS+sj];
        qsum += v*v; ts += v;
      }
      tsum += ts*ts;
    }
    float Sq = blk_sum512(qsum, sm);
    float T2 = blk_sum512(tsum, sm);
    if(tid==0 && out_size > B_*S_*H_*OH_)
      out[B_*S_*H_*OH_] = ((float)B_*Sq - T2) / (float)((B_-1)*(B_-1)) / (float)SS;
  }
}

// ---------------- launcher ----------------
extern "C" void kernel_launch(void* const* d_in, const int* in_sizes, int n_in,
                              void* d_out, int out_size){
  const float* x      = (const float*)d_in[0];
  const float* times  = (const float*)d_in[1];
  const float* mask   = (const float*)d_in[2];
  const float* bn_g   = (const float*)d_in[3];
  const float* bn_b   = (const float*)d_in[4];
  const float* obs    = (const float*)d_in[5];
  const float* attn_w = (const float*)d_in[6];
  const float* bidir_w= (const float*)d_in[7];
  const float* proj_W = (const float*)d_in[8];
  const float* proj_b = (const float*)d_in[9];
  const float* Wq     = (const float*)d_in[10];
  const float* bq     = (const float*)d_in[11];
  const float* Wk     = (const float*)d_in[12];
  const float* bk     = (const float*)d_in[13];
  const float* Ws     = (const float*)d_in[14];
  const float* bs     = (const float*)d_in[15];
  const float* lnt_g  = (const float*)d_in[16];
  const float* lnt_b  = (const float*)d_in[17];
  const float* Wse    = (const float*)d_in[18];
  const float* bse    = (const float*)d_in[19];
  const float* lns_g  = (const float*)d_in[20];
  const float* lns_b  = (const float*)d_in[21];
  float* out = (float*)d_out;

  k_pro<<<T_+1+8, 512>>>(x, bn_g, bn_b, mask, times, obs, bidir_w);
  k_layer<<<BH*T_, 256>>>(proj_W, proj_b, attn_w, 0);
  k_layer<<<BH*T_, 256>>>(proj_W, proj_b, attn_w + (size_t)H_*S_*AD_, 1);
  k_prune<<<BH*S_, 256>>>();
  k_msg1<<<BH*T_, 256>>>();
  k_beta<<<BH*S_, 256>>>(Wq, bq, Wk, bk, Ws, bs);
  k_final<<<BH, 512>>>(lnt_g, lnt_b, Wse, bse, lns_g, lns_b, out, out_size);
}

// round 12
// speedup vs baseline: 1.9900x; 1.2365x over previous
#include <cuda_runtime.h>

#define LRELU(v) ((v) >= 0.f ? (v) : 0.01f*(v))

constexpr int B_=8, T_=60, S_=36, H_=4, E_=16, PE_=16, AD_=12, D_=28, TA_=10, C_=32, OH_=16;
constexpr int BH = B_*H_;         // 32
constexpr int SS = S_*S_;         // 1296
constexpr int KEEP = 648;         // floor(S*S*0.5)
constexpr float EPSf = 1e-5f;

// ---------------- device scratch ----------------
__device__ float g_pe[B_*T_*PE_];
__device__ float g_rcnt[B_*S_];          // 1/cnt
__device__ float g_h[BH*T_*S_*E_];       // (b,h,t,s,e)
__device__ float g_alpha[BH*T_*SS];      // (b,h,t,s,j)  layer-1 only
__device__ float g_asum[BH*SS];          // t-sum of layer-1 alpha (atomic)
__device__ float g_adj[BH*SS];           // pruned adj
__device__ float g_bidir2[2*H_*SS];      // (lay,h,s,j)
__device__ float g_Hc[BH*S_*T_*C_];      // (b,h,s,t,d)
__device__ float g_beta[BH*S_*T_];       // (b,h,s,t)

__device__ __forceinline__ float blk_sum512(float v, float* sm){
  int tid = threadIdx.x;
  __syncthreads();
  sm[tid] = v; __syncthreads();
  #pragma unroll
  for(int s=256; s>0; s>>=1){ if(tid<s) sm[tid]+=sm[tid+s]; __syncthreads(); }
  return sm[0];
}

// ================= K0: prologue (BN+hinit | PE+rcnt | bidir + zero asum) =================
__global__ void k_pro(const float* __restrict__ x, const float* __restrict__ bn_g,
                      const float* __restrict__ bn_b, const float* __restrict__ mask,
                      const float* __restrict__ times, const float* __restrict__ obs,
                      const float* __restrict__ bw){
  int blk = blockIdx.x, tid = threadIdx.x;
  if(blk < T_){
    __shared__ float sm[512];
    __shared__ float xn[B_*S_], mk[B_*S_];
    __shared__ float sc_, sh_;
    int t = blk;
    float v = 0.f;
    if(tid < B_*S_){ int b=tid/S_, s=tid%S_; v = x[(b*T_+t)*S_+s]; }
    float sum = blk_sum512(v, sm);
    float sq  = blk_sum512(v*v, sm);
    if(tid==0){
      float n=(float)(B_*S_);
      float mu=sum/n; float var=sq/n-mu*mu;
      sc_=bn_g[t]*rsqrtf(var+EPSf); sh_=bn_b[t]-mu*sc_;
    }
    __syncthreads();
    if(tid < B_*S_){
      int b=tid/S_, s=tid%S_;
      xn[tid]=v*sc_+sh_;
      mk[tid]=mask[(b*T_+t)*S_+s];
    }
    __syncthreads();
    for(int idx=tid; idx<B_*H_*S_*E_; idx+=512){
      int e  = idx & 15;
      int s  = (idx>>4)%S_;
      int hh = (idx/(16*S_))%H_;
      int b  = idx/(16*S_*H_);
      float val = xn[b*S_+s]*obs[s*(E_*H_)+hh*E_+e];
      val = LRELU(val);
      g_h[((b*H_+hh)*T_+t)*(S_*E_) + s*E_+e] = val*mk[b*S_+s];
    }
  } else if(blk == T_){
    for(int idx=tid; idx<B_*T_*PE_; idx+=512){
      int k=idx&15; int t=(idx>>4)%T_; int b=idx/(16*T_);
      float div = expf(-(float)(k>>1)*1.1512925464970229f);
      float ang = times[b*T_+t]*div;
      g_pe[idx] = (k&1) ? cosf(ang) : sinf(ang);
    }
    if(tid < B_*S_){
      int b=tid/S_, s=tid%S_;
      float c=0.f;
      #pragma unroll 4
      for(int t=0;t<T_;t++) c += mask[(b*T_+t)*S_+s];
      g_rcnt[tid]=1.0f/c;
    }
  } else {
    int gid = (blk - (T_+1))*512 + tid;
    for(int idx=gid; idx<2*H_*SS; idx+=8*512){
      int lay = idx/(H_*SS);
      int r   = idx%(H_*SS);
      int hh  = r/SS; int s=(r/S_)%S_; int j=r%S_;
      const float* w = bw + (size_t)(lay*H_+hh)*S_*AD_;
      float sum=0.f;
      #pragma unroll
      for(int d=0; d<AD_; d++) sum += w[s*AD_+d]*w[j*AD_+d];
      g_bidir2[idx]=LRELU(sum);
    }
    for(int idx=gid; idx<BH*SS; idx+=8*512) g_asum[idx]=0.f;
  }
}

// ================= K1: fused per-(b,h,t): hp -> alpha (-> msg if lay0; store+atomic if lay1) ====
__global__ void k_layer(const float* __restrict__ W, const float* __restrict__ pb,
                        const float* __restrict__ aw, int lay){
  __shared__ float sh_h[S_*E_];
  __shared__ float sh_hp[S_*D_];
  __shared__ float sh_W[D_*E_];
  __shared__ float sh_b[D_];
  __shared__ float sh_aw[S_*AD_];
  __shared__ float sh_pe[PE_];
  __shared__ float sh_C[S_];
  __shared__ float sh_a[SS];
  int blk = blockIdx.x, tid = threadIdx.x;
  int bh = blk/T_, t = blk%T_;
  int b = bh/H_, hh = bh%H_;
  int hbase = blk*S_*E_;
  for(int i=tid;i<S_*E_;i+=256) sh_h[i]=g_h[hbase+i];
  for(int i=tid;i<D_*E_;i+=256) sh_W[i]=W[i];
  if(tid<D_) sh_b[tid]=pb[tid];
  for(int i=tid;i<S_*AD_;i+=256) sh_aw[i]=aw[hh*S_*AD_+i];
  if(tid<PE_) sh_pe[tid]=g_pe[(b*T_+t)*PE_+tid];
  __syncthreads();
  for(int o=tid;o<S_*32;o+=256){
    int s=o>>5, d=o&31;
    if(d<D_){
      float sum=sh_b[d];
      #pragma unroll
      for(int e=0;e<E_;e++) sum += sh_h[s*E_+e]*sh_W[d*E_+e];
      sh_hp[s*D_+d]=sum;
    }
  }
  __syncthreads();
  if(tid<S_){
    float c=0.f;
    #pragma unroll
    for(int d=0;d<PE_;d++) c += sh_hp[tid*D_+AD_+d]*sh_pe[d];
    sh_C[tid]=c;
  }
  __syncthreads();
  if(lay){
    int abase = blk*SS;
    int sbase = bh*SS;
    for(int o=tid;o<SS;o+=256){
      int s=o/S_, j=o-s*S_;
      float sum=sh_C[s];
      #pragma unroll
      for(int d=0;d<AD_;d++) sum += sh_hp[s*D_+d]*sh_aw[j*AD_+d];
      float a = LRELU(sum);
      g_alpha[abase+o]=a;
      atomicAdd(&g_asum[sbase+o], a);
    }
    return;
  }
  const float* bd = g_bidir2 + hh*SS;
  for(int o=tid;o<SS;o+=256){
    int s=o/S_, j=o-s*S_;
    float sum=sh_C[s];
    #pragma unroll
    for(int d=0;d<AD_;d++) sum += sh_hp[s*D_+d]*sh_aw[j*AD_+d];
    float a = LRELU(sum);
    sh_a[o] = LRELU(bd[o]*a);
  }
  __syncthreads();
  for(int o=tid;o<S_*E_;o+=256){
    int s=o>>4, e=o&15;
    float sum=0.f;
    #pragma unroll
    for(int j=0;j<S_;j++){
      float p = sh_h[j*E_+e]*sh_a[s*S_+j];
      sum += LRELU(p);
    }
    g_h[hbase+o]=LRELU(sum);
  }
}

// ================= K2: prune — one block per (b,h,row): grid=BH*36 =================
__global__ void k_prune(){
  __shared__ float vals[SS];
  __shared__ float rcnt[S_];
  int bh = blockIdx.x/S_;
  int row = blockIdx.x%S_;
  int tid = threadIdx.x;
  int b = bh/H_;
  if(tid<S_) rcnt[tid]=g_rcnt[b*S_+tid];
  __syncthreads();
  const float* src = g_asum + bh*SS;
  for(int i=tid;i<SS;i+=256){
    int s=i/S_;
    vals[i]=LRELU(src[i]*rcnt[s]);
  }
  __syncthreads();
  int wid = tid>>5, lane = tid&31;
  float* dst = g_adj + bh*SS;
  for(int e=wid; e<S_; e+=8){
    int i = row*S_ + e;
    float v = vals[i];
    int c=0;
    for(int j=lane;j<SS;j+=32){
      float vj = vals[j];
      c += (vj<v) || (vj==v && j<i);
    }
    #pragma unroll
    for(int o=16;o>0;o>>=1) c += __shfl_xor_sync(0xffffffffu, c, o);
    if(lane==0) dst[i] = (c>=KEEP) ? v : 0.f;
  }
}

// ================= K3: layer-1 message passing per (b,h,t) =================
__global__ void k_msg1(){
  __shared__ float sh_h[S_*E_];
  __shared__ float sh_w[SS];
  int blk = blockIdx.x, tid = threadIdx.x;
  int bh = blk/T_; int hh = bh%H_;
  int hbase = blk*S_*E_;
  int abase = blk*SS;
  const float* bd = g_bidir2 + (H_+hh)*SS;
  const float* ad = g_adj + bh*SS;
  for(int i=tid;i<S_*E_;i+=256) sh_h[i]=g_h[hbase+i];
  for(int o=tid;o<SS;o+=256){
    float w = bd[o]*g_alpha[abase+o]*ad[o];
    sh_w[o]=LRELU(w);
  }
  __syncthreads();
  for(int o=tid;o<S_*E_;o+=256){
    int s=o>>4, e=o&15;
    float sum=0.f;
    #pragma unroll
    for(int j=0;j<S_;j++){
      float p = sh_h[j*E_+e]*sh_w[s*S_+j];
      sum += LRELU(p);
    }
    g_h[hbase+o]=LRELU(sum);
  }
}

// ================= K4: Hc + factored beta, per (b,h,s) =================
// beta[t] = bs + bq·kt + Hc[t]·(Wq^T kt),  kt = Wk·m + (ΣWs)·bk,  m = Σ_t Ws_t Hc[t]
__global__ void k_beta(const float* __restrict__ Wq, const float* __restrict__ bq,
                       const float* __restrict__ Wk, const float* __restrict__ bk,
                       const float* __restrict__ Ws, const float* __restrict__ bs){
  __shared__ float Hc[T_*C_];   // 1920
  __shared__ float wss[T_];
  __shared__ float m[C_];
  __shared__ float kt[TA_];
  __shared__ float vq[C_];
  __shared__ float sWs_, c0_;
  int blk = blockIdx.x;
  int bh = blk/S_, s = blk%S_;
  int b = bh/H_;
  int tid = threadIdx.x;
  for(int o=tid;o<T_*C_;o+=blockDim.x){
    int t=o>>5, d=o&31;
    float v = (d<E_) ? g_h[(bh*T_+t)*S_*E_ + s*E_ + d]
                     : g_pe[(b*T_+t)*PE_ + (d-E_)];
    Hc[o]=v;
    g_Hc[blk*T_*C_+o]=v;
  }
  if(tid<T_) wss[tid]=Ws[tid];
  __syncthreads();
  // m[d] = sum_t wss[t]*Hc[t*C+d]; also sWs
  if(tid<C_){
    float sum=0.f;
    #pragma unroll 4
    for(int t=0;t<T_;t++) sum += wss[t]*Hc[t*C_+tid];
    m[tid]=sum;
  } else if(tid==C_){
    float sum=0.f;
    #pragma unroll
    for(int t=0;t<T_;t++) sum += wss[t];
    sWs_=sum;
  }
  __syncthreads();
  // kt[q] = Wk[q]·m + sWs*bk[q]
  if(tid<TA_){
    float sum=0.f;
    #pragma unroll
    for(int d=0;d<C_;d++) sum += Wk[tid*C_+d]*m[d];
    kt[tid]=sum + sWs_*bk[tid];
  }
  __syncthreads();
  // vq[d] = sum_q Wq[q*C+d]*kt[q];  c0 = bq·kt
  if(tid<C_){
    float sum=0.f;
    #pragma unroll
    for(int q=0;q<TA_;q++) sum += Wq[q*C_+tid]*kt[q];
    vq[tid]=sum;
  } else if(tid==C_){
    float sum=0.f;
    #pragma unroll
    for(int q=0;q<TA_;q++) sum += bq[q]*kt[q];
    c0_=sum;
  }
  __syncthreads();
  if(tid<T_){
    float sum = bs[0] + c0_;
    #pragma unroll
    for(int d=0;d<C_;d++) sum += Hc[tid*C_+d]*vq[d];
    g_beta[blk*T_+tid]=sum;
  }
}

// ================= K5: epilogue per (b,h) =================
__global__ void k_final(const float* __restrict__ lnt_g, const float* __restrict__ lnt_b,
                        const float* __restrict__ Wse, const float* __restrict__ bse,
                        const float* __restrict__ lns_g, const float* __restrict__ lns_b,
                        float* __restrict__ out, int out_size){
  __shared__ float sm[512];
  __shared__ float bet[S_*T_];
  __shared__ float o1s[S_*C_];
  __shared__ float o2s[S_*OH_];
  __shared__ float mu_, rs_;
  int bh = blockIdx.x, tid = threadIdx.x;
  int b = bh/H_, hh = bh%H_;
  float s1=0.f, s2=0.f;
  for(int i=tid;i<S_*T_;i+=512){ float v=g_beta[bh*S_*T_+i]; bet[i]=v; s1+=v; s2+=v*v; }
  float sum = blk_sum512(s1, sm);
  float sq  = blk_sum512(s2, sm);
  if(tid==0){ float n=(float)(S_*T_); float mu=sum/n; float var=sq/n-mu*mu; mu_=mu; rs_=rsqrtf(var+EPSf); }
  __syncthreads();
  for(int i=tid;i<S_*T_;i+=512) bet[i]=(bet[i]-mu_)*rs_*lnt_g[i]+lnt_b[i];
  __syncthreads();
  for(int o=tid;o<S_*C_;o+=512){
    int s=o>>5, d=o&31;
    const float* hc = g_Hc + ((size_t)(bh*S_+s)*T_)*C_ + d;
    float sum2=0.f;
    #pragma unroll 4
    for(int t=0;t<T_;t++) sum2 += bet[s*T_+t]*hc[(size_t)t*C_];
    o1s[o]=LRELU(sum2);
  }
  __syncthreads();
  float t1=0.f, t2=0.f;
  for(int o=tid;o<S_*OH_;o+=512){
    int s=o/OH_, q=o&15;
    float sum2=bse[q];
    #pragma unroll
    for(int d=0;d<C_;d++) sum2 += o1s[s*C_+d]*Wse[q*C_+d];
    float v=LRELU(sum2);
    o2s[o]=v; t1+=v; t2+=v*v;
  }
  float sum2a = blk_sum512(t1, sm);
  float sq2a  = blk_sum512(t2, sm);
  if(tid==0){ float n=(float)(S_*OH_); float mu=sum2a/n; float var=sq2a/n-mu*mu; mu_=mu; rs_=rsqrtf(var+EPSf); }
  __syncthreads();
  for(int o=tid;o<S_*OH_;o+=512){
    int s=o/OH_, q=o&15;
    float v = (o2s[o]-mu_)*rs_*lns_g[o]+lns_b[o];
    out[(b*S_+s)*(H_*OH_) + hh*OH_ + q]=v;
  }
  if(bh==0){
    float qsum=0.f, tsum=0.f;
    for(int pos=tid; pos<H_*SS; pos+=512){
      int hhh=pos/SS, sj=pos%SS;
      float ts=0.f;
      #pragma unroll
      for(int bb=0;bb<B_;bb++){
        float v = g_adj[(bb*H_+hhh)*SS+sj];
        qsum += v*v; ts += v;
      }
      tsum += ts*ts;
    }
    float Sq = blk_sum512(qsum, sm);
    float T2 = blk_sum512(tsum, sm);
    if(tid==0 && out_size > B_*S_*H_*OH_)
      out[B_*S_*H_*OH_] = ((float)B_*Sq - T2) / (float)((B_-1)*(B_-1)) / (float)SS;
  }
}

// ---------------- launcher ----------------
extern "C" void kernel_launch(void* const* d_in, const int* in_sizes, int n_in,
                              void* d_out, int out_size){
  const float* x      = (const float*)d_in[0];
  const float* times  = (const float*)d_in[1];
  const float* mask   = (const float*)d_in[2];
  const float* bn_g   = (const float*)d_in[3];
  const float* bn_b   = (const float*)d_in[4];
  const float* obs    = (const float*)d_in[5];
  const float* attn_w = (const float*)d_in[6];
  const float* bidir_w= (const float*)d_in[7];
  const float* proj_W = (const float*)d_in[8];
  const float* proj_b = (const float*)d_in[9];
  const float* Wq     = (const float*)d_in[10];
  const float* bq     = (const float*)d_in[11];
  const float* Wk     = (const float*)d_in[12];
  const float* bk     = (const float*)d_in[13];
  const float* Ws     = (const float*)d_in[14];
  const float* bs     = (const float*)d_in[15];
  const float* lnt_g  = (const float*)d_in[16];
  const float* lnt_b  = (const float*)d_in[17];
  const float* Wse    = (const float*)d_in[18];
  const float* bse    = (const float*)d_in[19];
  const float* lns_g  = (const float*)d_in[20];
  const float* lns_b  = (const float*)d_in[21];
  float* out = (float*)d_out;

  k_pro<<<T_+1+8, 512>>>(x, bn_g, bn_b, mask, times, obs, bidir_w);
  k_layer<<<BH*T_, 256>>>(proj_W, proj_b, attn_w, 0);
  k_layer<<<BH*T_, 256>>>(proj_W, proj_b, attn_w + (size_t)H_*S_*AD_, 1);
  k_prune<<<BH*S_, 256>>>();
  k_msg1<<<BH*T_, 256>>>();
  k_beta<<<BH*S_, 256>>>(Wq, bq, Wk, bk, Ws, bs);
  k_final<<<BH, 512>>>(lnt_g, lnt_b, Wse, bse, lns_g, lns_b, out, out_size);
}

// round 15
// speedup vs baseline: 2.3272x; 1.1694x over previous
#include <cuda_runtime.h>

#define LRELU(v) ((v) >= 0.f ? (v) : 0.01f*(v))

constexpr int B_=8, T_=60, S_=36, H_=4, E_=16, PE_=16, AD_=12, TA_=10, C_=32, OH_=16;
constexpr int BH = B_*H_;         // 32
constexpr int SS = S_*S_;         // 1296
constexpr int KEEP = 648;         // floor(S*S*0.5)
constexpr int EP = 17;            // padded awW row stride
constexpr float EPSf = 1e-5f;

// ---------------- device scratch ----------------
__device__ float g_pe[B_*T_*PE_];
__device__ float g_rcnt[B_*S_];          // 1/cnt
__device__ float g_h[BH*T_*S_*E_];       // (b,h,t,s,e)
__device__ float g_alpha[BH*T_*SS];      // (b,h,t,s,j)  layer-1 only
__device__ float g_asum[BH*SS];          // t-sum of layer-1 alpha (atomic)
__device__ float g_adj[BH*SS];           // pruned adj
__device__ float g_bidir2[2*H_*SS];      // (lay,h,s,j)
__device__ float g_awW[2*H_*S_*E_];      // (lay,h,j,e): aw[j,:12] @ W[:12,:]
__device__ float g_pbdot[2*H_*S_];       // (lay,h,j):   aw[j,:12] · pb[:12]
__device__ float g_Hc[BH*S_*T_*C_];      // (b,h,s,t,d)
__device__ float g_beta[BH*S_*T_];       // (b,h,s,t)

__device__ __forceinline__ float blk_sum512(float v, float* sm){
  int tid = threadIdx.x;
  __syncthreads();
  sm[tid] = v; __syncthreads();
  #pragma unroll
  for(int s=256; s>0; s>>=1){ if(tid<s) sm[tid]+=sm[tid+s]; __syncthreads(); }
  return sm[0];
}

// ================= K0: prologue (BN+hinit | PE+rcnt | bidir+awW+pbdot+zero asum) ==========
__global__ void k_pro(const float* __restrict__ x, const float* __restrict__ bn_g,
                      const float* __restrict__ bn_b, const float* __restrict__ mask,
                      const float* __restrict__ times, const float* __restrict__ obs,
                      const float* __restrict__ bw, const float* __restrict__ aw,
                      const float* __restrict__ W, const float* __restrict__ pb){
  int blk = blockIdx.x, tid = threadIdx.x;
  if(blk < T_){
    __shared__ float sm[512];
    __shared__ float xn[B_*S_], mk[B_*S_];
    __shared__ float sc_, sh_;
    int t = blk;
    float v = 0.f;
    if(tid < B_*S_){ int b=tid/S_, s=tid%S_; v = x[(b*T_+t)*S_+s]; }
    float sum = blk_sum512(v, sm);
    float sq  = blk_sum512(v*v, sm);
    if(tid==0){
      float n=(float)(B_*S_);
      float mu=sum/n; float var=sq/n-mu*mu;
      sc_=bn_g[t]*rsqrtf(var+EPSf); sh_=bn_b[t]-mu*sc_;
    }
    __syncthreads();
    if(tid < B_*S_){
      int b=tid/S_, s=tid%S_;
      xn[tid]=v*sc_+sh_;
      mk[tid]=mask[(b*T_+t)*S_+s];
    }
    __syncthreads();
    for(int idx=tid; idx<B_*H_*S_*E_; idx+=512){
      int e  = idx & 15;
      int s  = (idx>>4)%S_;
      int hh = (idx/(16*S_))%H_;
      int b  = idx/(16*S_*H_);
      float val = xn[b*S_+s]*obs[s*(E_*H_)+hh*E_+e];
      val = LRELU(val);
      g_h[((b*H_+hh)*T_+t)*(S_*E_) + s*E_+e] = val*mk[b*S_+s];
    }
  } else if(blk == T_){
    for(int idx=tid; idx<B_*T_*PE_; idx+=512){
      int k=idx&15; int t=(idx>>4)%T_; int b=idx/(16*T_);
      float div = expf(-(float)(k>>1)*1.1512925464970229f);
      float ang = times[b*T_+t]*div;
      g_pe[idx] = (k&1) ? cosf(ang) : sinf(ang);
    }
    if(tid < B_*S_){
      int b=tid/S_, s=tid%S_;
      float c=0.f;
      #pragma unroll 4
      for(int t=0;t<T_;t++) c += mask[(b*T_+t)*S_+s];
      g_rcnt[tid]=1.0f/c;
    }
  } else {
    int gid = (blk - (T_+1))*512 + tid;
    for(int idx=gid; idx<2*H_*SS; idx+=8*512){
      int lay = idx/(H_*SS);
      int r   = idx%(H_*SS);
      int hh  = r/SS; int s=(r/S_)%S_; int j=r%S_;
      const float* w = bw + (size_t)(lay*H_+hh)*S_*AD_;
      float sum=0.f;
      #pragma unroll
      for(int d=0; d<AD_; d++) sum += w[s*AD_+d]*w[j*AD_+d];
      g_bidir2[idx]=LRELU(sum);
    }
    // awW[lay,hh,j,e] = sum_{d<12} aw[lay,hh,j,d] * W[d,e]
    for(int idx=gid; idx<2*H_*S_*E_; idx+=8*512){
      int e = idx & 15;
      int j = (idx>>4)%S_;
      int hh = (idx/(16*S_))%H_;
      int lay = idx/(16*S_*H_);
      const float* a = aw + (size_t)((lay*H_+hh)*S_+j)*AD_;
      float sum=0.f;
      #pragma unroll
      for(int d=0; d<AD_; d++) sum += a[d]*W[d*E_+e];
      g_awW[idx]=sum;
    }
    // pbdot[lay,hh,j] = aw[j,:12] . pb[:12]
    for(int idx=gid; idx<2*H_*S_; idx+=8*512){
      int j = idx%S_;
      int hh = (idx/S_)%H_;
      int lay = idx/(S_*H_);
      const float* a = aw + (size_t)((lay*H_+hh)*S_+j)*AD_;
      float sum=0.f;
      #pragma unroll
      for(int d=0; d<AD_; d++) sum += a[d]*pb[d];
      g_pbdot[idx]=sum;
    }
    for(int idx=gid; idx<BH*SS; idx+=8*512) g_asum[idx]=0.f;
  }
}

// ================= K1: fused per-(b,h,t): alpha direct from h (no hp GEMM) ====
__global__ void k_layer(const float* __restrict__ W, const float* __restrict__ pb, int lay){
  __shared__ float sh_h[S_*E_];     // 576
  __shared__ float sh_awW[S_*EP];   // 612 padded
  __shared__ float sh_pbd[S_];
  __shared__ float sh_pe[PE_];
  __shared__ float sh_wpe[E_];
  __shared__ float sh_C[S_];
  __shared__ float sh_a[SS];
  __shared__ float cpec;
  int blk = blockIdx.x, tid = threadIdx.x;
  int bh = blk/T_, t = blk%T_;
  int b = bh/H_, hh = bh%H_;
  int hbase = blk*S_*E_;
  const float* awW = g_awW + (size_t)(lay*H_+hh)*S_*E_;
  const float* pbd = g_pbdot + (size_t)(lay*H_+hh)*S_;
  for(int i=tid;i<S_*E_;i+=256){
    sh_h[i]=g_h[hbase+i];
    sh_awW[(i>>4)*EP + (i&15)] = awW[i];
  }
  if(tid<S_) sh_pbd[tid]=pbd[tid];
  if(tid<PE_) sh_pe[tid]=g_pe[(b*T_+t)*PE_+tid];
  __syncthreads();
  if(tid<E_){
    float sum=0.f;
    #pragma unroll
    for(int k=0;k<PE_;k++) sum += sh_pe[k]*W[(AD_+k)*E_+tid];
    sh_wpe[tid]=sum;
  } else if(tid==E_){
    float sum=0.f;
    #pragma unroll
    for(int k=0;k<PE_;k++) sum += sh_pe[k]*pb[AD_+k];
    cpec=sum;
  }
  __syncthreads();
  if(tid<S_){
    float c=cpec;
    #pragma unroll
    for(int e=0;e<E_;e++) c += sh_h[tid*E_+e]*sh_wpe[e];
    sh_C[tid]=c;
  }
  __syncthreads();
  if(lay){
    int abase = blk*SS;
    int sbase = bh*SS;
    for(int o=tid;o<SS;o+=256){
      int s=o/S_, j=o-s*S_;
      float sum=sh_C[s]+sh_pbd[j];
      #pragma unroll
      for(int e=0;e<E_;e++) sum += sh_h[s*E_+e]*sh_awW[j*EP+e];
      float a = LRELU(sum);
      g_alpha[abase+o]=a;
      atomicAdd(&g_asum[sbase+o], a);
    }
    return;
  }
  const float* bd = g_bidir2 + hh*SS;
  for(int o=tid;o<SS;o+=256){
    int s=o/S_, j=o-s*S_;
    float sum=sh_C[s]+sh_pbd[j];
    #pragma unroll
    for(int e=0;e<E_;e++) sum += sh_h[s*E_+e]*sh_awW[j*EP+e];
    float a = LRELU(sum);
    sh_a[o] = LRELU(bd[o]*a);
  }
  __syncthreads();
  for(int o=tid;o<S_*E_;o+=256){
    int s=o>>4, e=o&15;
    float sum=0.f;
    #pragma unroll
    for(int j=0;j<S_;j++){
      float p = sh_h[j*E_+e]*sh_a[s*S_+j];
      sum += LRELU(p);
    }
    g_h[hbase+o]=LRELU(sum);
  }
}

// ================= K2: prune — one block per (b,h,row): grid=BH*36 =================
__global__ void k_prune(){
  __shared__ float vals[SS];
  __shared__ float rcnt[S_];
  int bh = blockIdx.x/S_;
  int row = blockIdx.x%S_;
  int tid = threadIdx.x;
  int b = bh/H_;
  if(tid<S_) rcnt[tid]=g_rcnt[b*S_+tid];
  __syncthreads();
  const float* src = g_asum + bh*SS;
  for(int i=tid;i<SS;i+=256){
    int s=i/S_;
    vals[i]=LRELU(src[i]*rcnt[s]);
  }
  __syncthreads();
  int wid = tid>>5, lane = tid&31;
  float* dst = g_adj + bh*SS;
  for(int e=wid; e<S_; e+=8){
    int i = row*S_ + e;
    float v = vals[i];
    int c=0;
    for(int j=lane;j<SS;j+=32){
      float vj = vals[j];
      c += (vj<v) || (vj==v && j<i);
    }
    #pragma unroll
    for(int o=16;o>0;o>>=1) c += __shfl_xor_sync(0xffffffffu, c, o);
    if(lane==0) dst[i] = (c>=KEEP) ? v : 0.f;
  }
}

// ================= K3: layer-1 message passing per (b,h,t) =================
__global__ void k_msg1(){
  __shared__ float sh_h[S_*E_];
  __shared__ float sh_w[SS];
  int blk = blockIdx.x, tid = threadIdx.x;
  int bh = blk/T_; int hh = bh%H_;
  int hbase = blk*S_*E_;
  int abase = blk*SS;
  const float* bd = g_bidir2 + (H_+hh)*SS;
  const float* ad = g_adj + bh*SS;
  for(int i=tid;i<S_*E_;i+=256) sh_h[i]=g_h[hbase+i];
  for(int o=tid;o<SS;o+=256){
    float w = bd[o]*g_alpha[abase+o]*ad[o];
    sh_w[o]=LRELU(w);
  }
  __syncthreads();
  for(int o=tid;o<S_*E_;o+=256){
    int s=o>>4, e=o&15;
    float sum=0.f;
    #pragma unroll
    for(int j=0;j<S_;j++){
      float p = sh_h[j*E_+e]*sh_w[s*S_+j];
      sum += LRELU(p);
    }
    g_h[hbase+o]=LRELU(sum);
  }
}

// ================= K4: Hc + factored beta, per (b,h,s) =================
__global__ void k_beta(const float* __restrict__ Wq, const float* __restrict__ bq,
                       const float* __restrict__ Wk, const float* __restrict__ bk,
                       const float* __restrict__ Ws, const float* __restrict__ bs){
  __shared__ float Hc[T_*C_];   // 1920
  __shared__ float wss[T_];
  __shared__ float m[C_];
  __shared__ float kt[TA_];
  __shared__ float vq[C_];
  __shared__ float sWs_, c0_;
  int blk = blockIdx.x;
  int bh = blk/S_, s = blk%S_;
  int b = bh/H_;
  int tid = threadIdx.x;
  for(int o=tid;o<T_*C_;o+=blockDim.x){
    int t=o>>5, d=o&31;
    float v = (d<E_) ? g_h[(bh*T_+t)*S_*E_ + s*E_ + d]
                     : g_pe[(b*T_+t)*PE_ + (d-E_)];
    Hc[o]=v;
    g_Hc[blk*T_*C_+o]=v;
  }
  if(tid<T_) wss[tid]=Ws[tid];
  __syncthreads();
  if(tid<C_){
    float sum=0.f;
    #pragma unroll 4
    for(int t=0;t<T_;t++) sum += wss[t]*Hc[t*C_+tid];
    m[tid]=sum;
  } else if(tid==C_){
    float sum=0.f;
    #pragma unroll
    for(int t=0;t<T_;t++) sum += wss[t];
    sWs_=sum;
  }
  __syncthreads();
  if(tid<TA_){
    float sum=0.f;
    #pragma unroll
    for(int d=0;d<C_;d++) sum += Wk[tid*C_+d]*m[d];
    kt[tid]=sum + sWs_*bk[tid];
  }
  __syncthreads();
  if(tid<C_){
    float sum=0.f;
    #pragma unroll
    for(int q=0;q<TA_;q++) sum += Wq[q*C_+tid]*kt[q];
    vq[tid]=sum;
  } else if(tid==C_){
    float sum=0.f;
    #pragma unroll
    for(int q=0;q<TA_;q++) sum += bq[q]*kt[q];
    c0_=sum;
  }
  __syncthreads();
  if(tid<T_){
    float sum = bs[0] + c0_;
    #pragma unroll
    for(int d=0;d<C_;d++) sum += Hc[tid*C_+d]*vq[d];
    g_beta[blk*T_+tid]=sum;
  }
}

// ================= K5: epilogue per (b,h) =================
__global__ void k_final(const float* __restrict__ lnt_g, const float* __restrict__ lnt_b,
                        const float* __restrict__ Wse, const float* __restrict__ bse,
                        const float* __restrict__ lns_g, const float* __restrict__ lns_b,
                        float* __restrict__ out, int out_size){
  __shared__ float sm[512];
  __shared__ float bet[S_*T_];
  __shared__ float o1s[S_*C_];
  __shared__ float o2s[S_*OH_];
  __shared__ float mu_, rs_;
  int bh = blockIdx.x, tid = threadIdx.x;
  int b = bh/H_, hh = bh%H_;
  float s1=0.f, s2=0.f;
  for(int i=tid;i<S_*T_;i+=512){ float v=g_beta[bh*S_*T_+i]; bet[i]=v; s1+=v; s2+=v*v; }
  float sum = blk_sum512(s1, sm);
  float sq  = blk_sum512(s2, sm);
  if(tid==0){ float n=(float)(S_*T_); float mu=sum/n; float var=sq/n-mu*mu; mu_=mu; rs_=rsqrtf(var+EPSf); }
  __syncthreads();
  for(int i=tid;i<S_*T_;i+=512) bet[i]=(bet[i]-mu_)*rs_*lnt_g[i]+lnt_b[i];
  __syncthreads();
  for(int o=tid;o<S_*C_;o+=512){
    int s=o>>5, d=o&31;
    const float* hc = g_Hc + ((size_t)(bh*S_+s)*T_)*C_ + d;
    float sum2=0.f;
    #pragma unroll 4
    for(int t=0;t<T_;t++) sum2 += bet[s*T_+t]*hc[(size_t)t*C_];
    o1s[o]=LRELU(sum2);
  }
  __syncthreads();
  float t1=0.f, t2=0.f;
  for(int o=tid;o<S_*OH_;o+=512){
    int s=o/OH_, q=o&15;
    float sum2=bse[q];
    #pragma unroll
    for(int d=0;d<C_;d++) sum2 += o1s[s*C_+d]*Wse[q*C_+d];
    float v=LRELU(sum2);
    o2s[o]=v; t1+=v; t2+=v*v;
  }
  float sum2a = blk_sum512(t1, sm);
  float sq2a  = blk_sum512(t2, sm);
  if(tid==0){ float n=(float)(S_*OH_); float mu=sum2a/n; float var=sq2a/n-mu*mu; mu_=mu; rs_=rsqrtf(var+EPSf); }
  __syncthreads();
  for(int o=tid;o<S_*OH_;o+=512){
    int s=o/OH_, q=o&15;
    float v = (o2s[o]-mu_)*rs_*lns_g[o]+lns_b[o];
    out[(b*S_+s)*(H_*OH_) + hh*OH_ + q]=v;
  }
  if(bh==0){
    float qsum=0.f, tsum=0.f;
    for(int pos=tid; pos<H_*SS; pos+=512){
      int hhh=pos/SS, sj=pos%SS;
      float ts=0.f;
      #pragma unroll
      for(int bb=0;bb<B_;bb++){
        float v = g_adj[(bb*H_+hhh)*SS+sj];
        qsum += v*v; ts += v;
      }
      tsum += ts*ts;
    }
    float Sq = blk_sum512(qsum, sm);
    float T2 = blk_sum512(tsum, sm);
    if(tid==0 && out_size > B_*S_*H_*OH_)
      out[B_*S_*H_*OH_] = ((float)B_*Sq - T2) / (float)((B_-1)*(B_-1)) / (float)SS;
  }
}

// ---------------- launcher ----------------
extern "C" void kernel_launch(void* const* d_in, const int* in_sizes, int n_in,
                              void* d_out, int out_size){
  const float* x      = (const float*)d_in[0];
  const float* times  = (const float*)d_in[1];
  const float* mask   = (const float*)d_in[2];
  const float* bn_g   = (const float*)d_in[3];
  const float* bn_b   = (const float*)d_in[4];
  const float* obs    = (const float*)d_in[5];
  const float* attn_w = (const float*)d_in[6];
  const float* bidir_w= (const float*)d_in[7];
  const float* proj_W = (const float*)d_in[8];
  const float* proj_b = (const float*)d_in[9];
  const float* Wq     = (const float*)d_in[10];
  const float* bq     = (const float*)d_in[11];
  const float* Wk     = (const float*)d_in[12];
  const float* bk     = (const float*)d_in[13];
  const float* Ws     = (const float*)d_in[14];
  const float* bs     = (const float*)d_in[15];
  const float* lnt_g  = (const float*)d_in[16];
  const float* lnt_b  = (const float*)d_in[17];
  const float* Wse    = (const float*)d_in[18];
  const float* bse    = (const float*)d_in[19];
  const float* lns_g  = (const float*)d_in[20];
  const float* lns_b  = (const float*)d_in[21];
  float* out = (float*)d_out;

  k_pro<<<T_+1+8, 512>>>(x, bn_g, bn_b, mask, times, obs, bidir_w, attn_w, proj_W, proj_b);
  k_layer<<<BH*T_, 256>>>(proj_W, proj_b, 0);
  k_layer<<<BH*T_, 256>>>(proj_W, proj_b, 1);
  k_prune<<<BH*S_, 256>>>();
  k_msg1<<<BH*T_, 256>>>();
  k_beta<<<BH*S_, 256>>>(Wq, bq, Wk, bk, Ws, bs);
  k_final<<<BH, 512>>>(lnt_g, lnt_b, Wse, bse, lns_g, lns_b, out, out_size);
}